// round 16
// baseline (speedup 1.0000x reference)
#include <cuda_runtime.h>
#include <cuda_bf16.h>
#include <cstdint>

// MemoryTemporalBlock — bf16 m16n8k16 everywhere, MMA-based attention.
// R15: B-fragments repacked for LDG.128 (2 loads/k-step instead of 4) and
// vectorized LayerNorm (float4 LDS/LDG/STG, gamma/beta hoisted).
// One CTA per 4 (b,n) tiles (M=48 = 3 m16-tiles), 256 threads, ~103KB smem,
// 2 CTAs/SM. vb pad rows (48..55) zeroed (tau=3 V ldmatrix reads them).

#define TT 12
#define DD 256
#define GG 4
#define MROWS (GG * TT)   // 48
#define LDPH 132          // bf16 buffer stride in uints (bf16x2)
#define LDPF 260          // fp32 pre-LN stride (floats)
#define MMM 8
#define LOG2E 1.4426950408889634f

// Wfrag[mat][wn(8)][kstep(16)][lane(32)][ntile(4)] as uint2 — 32B/lane/k-step
__device__ uint2 g_Wfrag[4][8][16][32][4];
// mem_k B-fragments: [head][kstep(2)][lane]  (n = m slot, k = dk)
__device__ uint2 g_Mfrag[8][2][32];
// mem_v B-fragments: [head][ntile(4)][lane]  (n = dk col, k = m slot; k 8-15 = 0)
__device__ uint2 g_Vmfrag[8][4][32];

static __device__ __forceinline__ uint32_t pkbf(float lo, float hi) {
    __nv_bfloat162 h = __float22bfloat162_rn(make_float2(lo, hi));
    uint32_t r; memcpy(&r, &h, 4); return r;
}
static __device__ __forceinline__ float ex2(float x) {
    float r; asm("ex2.approx.f32 %0, %1;" : "=f"(r) : "f"(x)); return r;
}
static __device__ __forceinline__ void ldsm4(uint32_t* a, uint32_t saddr) {
    asm volatile("ldmatrix.sync.aligned.m8n8.x4.shared.b16 {%0,%1,%2,%3}, [%4];"
        : "=r"(a[0]), "=r"(a[1]), "=r"(a[2]), "=r"(a[3]) : "r"(saddr));
}
static __device__ __forceinline__ void ldsm2t(uint32_t* a, uint32_t saddr) {
    asm volatile("ldmatrix.sync.aligned.m8n8.x2.trans.shared.b16 {%0,%1}, [%2];"
        : "=r"(a[0]), "=r"(a[1]) : "r"(saddr));
}
static __device__ __forceinline__ void mma_bf16(float* c, const uint32_t* a,
                                                uint32_t b0, uint32_t b1) {
    asm("mma.sync.aligned.m16n8k16.row.col.f32.bf16.bf16.f32 "
        "{%0,%1,%2,%3}, {%4,%5,%6,%7}, {%8,%9}, {%0,%1,%2,%3};"
        : "+f"(c[0]), "+f"(c[1]), "+f"(c[2]), "+f"(c[3])
        : "r"(a[0]), "r"(a[1]), "r"(a[2]), "r"(a[3]), "r"(b0), "r"(b1));
}
static __device__ __forceinline__ float warp_sum(float v) {
#pragma unroll
    for (int o = 16; o; o >>= 1) v += __shfl_xor_sync(0xffffffffu, v, o);
    return v;
}
static __device__ __forceinline__ float gsum4(float v) {
    v += __shfl_xor_sync(0xffffffffu, v, 1);
    v += __shfl_xor_sync(0xffffffffu, v, 2);
    return v;
}

__global__ void prep_kernel(const float* __restrict__ wq, const float* __restrict__ wk,
                            const float* __restrict__ wv, const float* __restrict__ wf)
{
    int i = blockIdx.x * blockDim.x + threadIdx.x;   // 65536 threads
    int lane = i & 31;
    int nt   = (i >> 5) & 3;
    int kk   = (i >> 7) & 15;
    int wn   = (i >> 11) & 7;
    int mat  = i >> 14;
    const float* W = (mat == 0) ? wq : (mat == 1) ? wk : (mat == 2) ? wv : wf;
    int e = wn * 32 + nt * 8 + (lane >> 2);
    int d = kk * 16 + (lane & 3) * 2;
    uint2 v;
    v.x = pkbf(__ldg(W + e * DD + d),     __ldg(W + e * DD + d + 1));
    v.y = pkbf(__ldg(W + e * DD + d + 8), __ldg(W + e * DD + d + 9));
    g_Wfrag[mat][wn][kk][lane][nt] = v;
}

__global__ void memprep_kernel(const float* __restrict__ memk,
                               const float* __restrict__ memv)
{
    int i = blockIdx.x * blockDim.x + threadIdx.x;   // 1536 threads
    if (i < 512) {
        int lane = i & 31, kk = (i >> 5) & 1, h = i >> 6;
        int n = lane >> 2, k0 = kk * 16 + (lane & 3) * 2;
        const float* base = memk + (h * MMM + n) * 32;
        uint2 v;
        v.x = pkbf(__ldg(base + k0),     __ldg(base + k0 + 1));
        v.y = pkbf(__ldg(base + k0 + 8), __ldg(base + k0 + 9));
        g_Mfrag[h][kk][lane] = v;
    } else if (i < 1536) {
        int j = i - 512;
        int lane = j & 31, nt = (j >> 5) & 3, h = j >> 7;
        int d = nt * 8 + (lane >> 2), m0 = (lane & 3) * 2;
        uint2 v;
        v.x = pkbf(__ldg(memv + (h * MMM + m0) * 32 + d),
                   __ldg(memv + (h * MMM + m0 + 1) * 32 + d));
        v.y = 0u;   // k (m) 8-15 do not exist -> zero
        g_Vmfrag[h][nt][lane] = v;
    }
}

// GEMM sweep over K=256; A = packed bf16 smem (shared addr), 3 m-tiles (M=48).
// B fragments: 2x LDG.128 per k-step (uint4 pairs), distance-2 prefetch.
static __device__ __forceinline__ void gemm_sweep(
    uint32_t abase, int lane,
    const uint4* __restrict__ Bp4,     // &g_Wfrag[mat][w][0][0][0]
    float acc[3][4][4])
{
#pragma unroll
    for (int mt = 0; mt < 3; mt++)
#pragma unroll
        for (int nt = 0; nt < 4; nt++)
#pragma unroll
            for (int j = 0; j < 4; j++) acc[mt][nt][j] = 0.f;

    uint4 b0a, b0b, b1a, b1b;
    b0a = __ldg(Bp4 + (0 * 32 + lane) * 2);
    b0b = __ldg(Bp4 + (0 * 32 + lane) * 2 + 1);
    b1a = __ldg(Bp4 + (1 * 32 + lane) * 2);
    b1b = __ldg(Bp4 + (1 * 32 + lane) * 2 + 1);

    const int arow = (lane & 7) + ((lane >> 3) & 1) * 8;
    const uint32_t alane = abase + (uint32_t)(arow * LDPH * 4) + ((lane >> 4) * 16);

#pragma unroll 4
    for (int kk = 0; kk < 16; kk++) {
        uint32_t a[3][4];
#pragma unroll
        for (int mt = 0; mt < 3; mt++)
            ldsm4(a[mt], alane + (uint32_t)(mt * 16 * LDPH * 4) + (uint32_t)(kk * 32));
        const uint4 bca = b0a, bcb = b0b;
        b0a = b1a; b0b = b1b;
        if (kk < 14) {
            b1a = __ldg(Bp4 + ((kk + 2) * 32 + lane) * 2);
            b1b = __ldg(Bp4 + ((kk + 2) * 32 + lane) * 2 + 1);
        }
#pragma unroll
        for (int mt = 0; mt < 3; mt++) {
            mma_bf16(acc[mt][0], a[mt], bca.x, bca.y);
            mma_bf16(acc[mt][1], a[mt], bca.z, bca.w);
            mma_bf16(acc[mt][2], a[mt], bcb.x, bcb.y);
            mma_bf16(acc[mt][3], a[mt], bcb.z, bcb.w);
        }
    }
}

// Store accumulators (+bias) as packed bf16 into a [48][LDPH] buffer.
static __device__ __forceinline__ void store_accb(
    uint32_t* __restrict__ dst, const float* __restrict__ bias,
    int w, int lane, const float acc[3][4][4])
{
#pragma unroll
    for (int nt = 0; nt < 4; nt++) {
        const int col = w * 32 + nt * 8 + 2 * (lane & 3);
        const float2 cb = __ldg((const float2*)(bias + col));
        const int cu = col >> 1;
#pragma unroll
        for (int mt = 0; mt < 3; mt++) {
            const int r0 = mt * 16 + (lane >> 2);
#pragma unroll
            for (int h2 = 0; h2 < 2; h2++) {
                const int r = r0 + 8 * h2;
                dst[r * LDPH + cu] =
                    pkbf(acc[mt][nt][2 * h2] + cb.x, acc[mt][nt][2 * h2 + 1] + cb.y);
            }
        }
    }
}

__global__ void __launch_bounds__(256, 2)
mtb_kernel(const float* __restrict__ x,
           const float* __restrict__ bq, const float* __restrict__ bk,
           const float* __restrict__ bv,
           const float* __restrict__ bf,
           const float* __restrict__ gamma, const float* __restrict__ beta,
           const float* __restrict__ alpha_p,
           float* __restrict__ out)
{
    extern __shared__ uint32_t smu[];
    uint32_t* xb = smu;                     // bf16 x            [48][132]
    uint32_t* qb = smu + 1 * MROWS * LDPH;  // bf16 Q -> attn out
    uint32_t* kb = smu + 2 * MROWS * LDPH;  // bf16 K
    uint32_t* vb = smu + 3 * MROWS * LDPH;  // bf16 V (+8 pad rows after)
    float*   pre = (float*)kb;              // fp32 pre-LN (overlays K,V after attention)

    const uint32_t qb_s = (uint32_t)__cvta_generic_to_shared(qb);
    const uint32_t kb_s = (uint32_t)__cvta_generic_to_shared(kb);
    const uint32_t vb_s = (uint32_t)__cvta_generic_to_shared(vb);
    const uint32_t xb_s = (uint32_t)__cvta_generic_to_shared(xb);

    const int tid  = threadIdx.x;
    const int w    = tid >> 5;
    const int lane = tid & 31;
    const size_t gbase = (size_t)blockIdx.x * (MROWS * DD);

    // ---- stage x as packed bf16; zero vb pad rows (read by tau=3 V ldmatrix) ----
    {
        const float4* xg = (const float4*)(x + gbase);
#pragma unroll
        for (int p = 0; p < 12; p++) {
            const int idx = p * 256 + tid;
            const int r = idx >> 6, cg = idx & 63;
            const float4 xv = xg[idx];
            xb[r * LDPH + cg * 2]     = pkbf(xv.x, xv.y);
            xb[r * LDPH + cg * 2 + 1] = pkbf(xv.z, xv.w);
        }
        for (int i = tid; i < 8 * LDPH; i += 256)
            vb[MROWS * LDPH + i] = 0u;
    }
    __syncthreads();

    // ---- sweeps: Q, K, V ----
    {
        float acc[3][4][4];
        gemm_sweep(xb_s, lane, (const uint4*)&g_Wfrag[0][w][0][0][0], acc);
        store_accb(qb, bq, w, lane, acc);
        gemm_sweep(xb_s, lane, (const uint4*)&g_Wfrag[1][w][0][0][0], acc);
        store_accb(kb, bk, w, lane, acc);
        gemm_sweep(xb_s, lane, (const uint4*)&g_Wfrag[2][w][0][0][0], acc);
        store_accb(vb, bv, w, lane, acc);
    }
    __syncthreads();

    // ---- attention via MMA: 32 units (tile,head); warp w -> units 4w..4w+3 ----
    const float sl = 0.17677669529663687f * LOG2E;
    const float wl = 1.f / (1.f + __expf(-__ldg(alpha_p)));
    const float wt = 1.f - wl;

    const int g  = lane >> 2;        // C/A fragment row group
    const int q2 = (lane & 3) * 2;   // C/A fragment col base
    const bool k00 = (q2     <= g);             // P0 row g,  s=q2
    const bool k01 = (q2 + 1 <= g);             // P0 row g,  s=q2+1
    const bool k12 = (q2     <= g) && (q2 < 4); // P1 row g+8, s=8+q2 (pad s<12)
    const bool k13 = (q2 + 1 <= g) && (q2 + 1 < 4);
    const int arow = (lane & 7) + ((lane >> 3) & 1) * 8;
    const int ahalf = (lane >> 4) * 16;

#pragma unroll
    for (int u = 0; u < 4; u++) {
        const int unit = w * 4 + u;
        const int tau = unit >> 3, h = unit & 7;
        const int rb = tau * TT;
        const uint32_t rowoff = (uint32_t)((rb + arow) * LDPH * 4) + (uint32_t)(h * 64 + ahalf);

        uint32_t aq[2][4], bk2[2][4];
        ldsm4(aq[0], qb_s + rowoff);
        ldsm4(aq[1], qb_s + rowoff + 32);
        ldsm4(bk2[0], kb_s + rowoff);
        ldsm4(bk2[1], kb_s + rowoff + 32);

        float S0[4] = {0.f, 0.f, 0.f, 0.f}, S1[4] = {0.f, 0.f, 0.f, 0.f};
        mma_bf16(S0, aq[0], bk2[0][0], bk2[0][2]);
        mma_bf16(S0, aq[1], bk2[1][0], bk2[1][2]);
        mma_bf16(S1, aq[0], bk2[0][1], bk2[0][3]);
        mma_bf16(S1, aq[1], bk2[1][1], bk2[1][3]);

        const float p00 = k00 ? ex2(S0[0] * sl) : 0.f;
        const float p01 = k01 ? ex2(S0[1] * sl) : 0.f;
        const float p02 = ex2(S0[2] * sl);
        const float p03 = ex2(S0[3] * sl);
        const float p12 = k12 ? ex2(S1[2] * sl) : 0.f;
        const float p13 = k13 ? ex2(S1[3] * sl) : 0.f;
        const float den_g  = gsum4(p00 + p01);
        const float den_g8 = gsum4(p02 + p03 + p12 + p13);

        uint32_t ap[4];
        ap[0] = pkbf(p00, p01);
        ap[1] = pkbf(p02, p03);
        ap[2] = 0u;
        ap[3] = pkbf(p12, p13);

        const uint2 mb0 = __ldg(&g_Mfrag[h][0][lane]);
        const uint2 mb1 = __ldg(&g_Mfrag[h][1][lane]);
        float Sl[4] = {0.f, 0.f, 0.f, 0.f};
        mma_bf16(Sl, aq[0], mb0.x, mb0.y);
        mma_bf16(Sl, aq[1], mb1.x, mb1.y);
        const float pl0 = ex2(Sl[0] * sl), pl1 = ex2(Sl[1] * sl);
        const float pl2 = ex2(Sl[2] * sl), pl3 = ex2(Sl[3] * sl);
        const float dl_g  = gsum4(pl0 + pl1);
        const float dl_g8 = gsum4(pl2 + pl3);
        uint32_t apl[4];
        apl[0] = pkbf(pl0, pl1);
        apl[1] = pkbf(pl2, pl3);
        apl[2] = 0u;
        apl[3] = 0u;

        const float it_g  = wt / den_g,  it_g8 = wt / den_g8;
        const float il_g  = wl / dl_g,   il_g8 = wl / dl_g8;
        const uint32_t vrow = vb_s + (uint32_t)((rb + arow) * LDPH * 4) + (uint32_t)(h * 64);
#pragma unroll
        for (int nt = 0; nt < 4; nt++) {
            uint32_t bv2[2];
            ldsm2t(bv2, vrow + (uint32_t)(nt * 16));
            float O[4] = {0.f, 0.f, 0.f, 0.f};
            mma_bf16(O, ap, bv2[0], bv2[1]);
            const uint2 vm = __ldg(&g_Vmfrag[h][nt][lane]);
            float Ol[4] = {0.f, 0.f, 0.f, 0.f};
            mma_bf16(Ol, apl, vm.x, vm.y);

            const int cu = h * 16 + nt * 4 + (lane & 3);
            qb[(rb + g) * LDPH + cu] =
                pkbf(O[0] * it_g + Ol[0] * il_g, O[1] * it_g + Ol[1] * il_g);
            if (g < 4)
                qb[(rb + g + 8) * LDPH + cu] =
                    pkbf(O[2] * it_g8 + Ol[2] * il_g8, O[3] * it_g8 + Ol[3] * il_g8);
        }
    }
    __syncthreads();

    // ---- sweep: fc; epilogue writes fp32 (acc+bias) into pre (overlays K/V) ----
    {
        float acc[3][4][4];
        gemm_sweep(qb_s, lane, (const uint4*)&g_Wfrag[3][w][0][0][0], acc);
#pragma unroll
        for (int nt = 0; nt < 4; nt++) {
            const int col = w * 32 + nt * 8 + 2 * (lane & 3);
            const float2 cbf = __ldg((const float2*)(bf + col));
#pragma unroll
            for (int mt = 0; mt < 3; mt++) {
                const int r0 = mt * 16 + (lane >> 2);
#pragma unroll
                for (int h2 = 0; h2 < 2; h2++) {
                    const int r = r0 + 8 * h2;
                    *(float2*)(pre + r * LDPF + col) =
                        make_float2(acc[mt][nt][2 * h2] + cbf.x,
                                    acc[mt][nt][2 * h2 + 1] + cbf.y);
                }
            }
        }
    }
    __syncthreads();

    // ---- LayerNorm: 6 rows/warp, thread owns 8 contiguous cols (float4 x2) ----
    {
        const int c0 = lane * 8;
        const float4 gm0 = __ldg((const float4*)(gamma + c0));
        const float4 gm1 = __ldg((const float4*)(gamma + c0 + 4));
        const float4 bt0 = __ldg((const float4*)(beta + c0));
        const float4 bt1 = __ldg((const float4*)(beta + c0 + 4));
        for (int r = w * 6; r < w * 6 + 6; r++) {
            float4 a0 = *(const float4*)(pre + r * LDPF + c0);
            float4 a1 = *(const float4*)(pre + r * LDPF + c0 + 4);
            const float4 x0 = __ldg((const float4*)(x + gbase + (size_t)r * DD + c0));
            const float4 x1 = __ldg((const float4*)(x + gbase + (size_t)r * DD + c0 + 4));
            a0.x += x0.x; a0.y += x0.y; a0.z += x0.z; a0.w += x0.w;
            a1.x += x1.x; a1.y += x1.y; a1.z += x1.z; a1.w += x1.w;
            float s  = a0.x + a0.y + a0.z + a0.w + a1.x + a1.y + a1.z + a1.w;
            float s2 = a0.x * a0.x + a0.y * a0.y + a0.z * a0.z + a0.w * a0.w
                     + a1.x * a1.x + a1.y * a1.y + a1.z * a1.z + a1.w * a1.w;
            s = warp_sum(s); s2 = warp_sum(s2);
            const float mu = s * (1.f / 256.f);
            const float var = s2 * (1.f / 256.f) - mu * mu;
            const float inv = rsqrtf(var + 1e-5f);
            float4 o0, o1;
            o0.x = (a0.x - mu) * inv * gm0.x + bt0.x;
            o0.y = (a0.y - mu) * inv * gm0.y + bt0.y;
            o0.z = (a0.z - mu) * inv * gm0.z + bt0.z;
            o0.w = (a0.w - mu) * inv * gm0.w + bt0.w;
            o1.x = (a1.x - mu) * inv * gm1.x + bt1.x;
            o1.y = (a1.y - mu) * inv * gm1.y + bt1.y;
            o1.z = (a1.z - mu) * inv * gm1.z + bt1.z;
            o1.w = (a1.w - mu) * inv * gm1.w + bt1.w;
            *(float4*)(out + gbase + (size_t)r * DD + c0)     = o0;
            *(float4*)(out + gbase + (size_t)r * DD + c0 + 4) = o1;
        }
    }
}

extern "C" void kernel_launch(void* const* d_in, const int* in_sizes, int n_in,
                              void* d_out, int out_size)
{
    (void)in_sizes; (void)n_in; (void)out_size;
    const float* x     = (const float*)d_in[0];
    const float* Wq_w  = (const float*)d_in[1];
    const float* Wq_b  = (const float*)d_in[2];
    const float* Wk_w  = (const float*)d_in[3];
    const float* Wk_b  = (const float*)d_in[4];
    const float* Wv_w  = (const float*)d_in[5];
    const float* Wv_b  = (const float*)d_in[6];
    const float* mem_k = (const float*)d_in[7];
    const float* mem_v = (const float*)d_in[8];
    const float* fc_w  = (const float*)d_in[9];
    const float* fc_b  = (const float*)d_in[10];
    const float* gamma = (const float*)d_in[11];
    const float* beta  = (const float*)d_in[12];
    const float* alpha = (const float*)d_in[13];
    float* out = (float*)d_out;

    // 4 bf16 buffers [48][132] uints + 8 pad rows (ldmatrix overrun at tau=3)
    const int smemBytes = (4 * MROWS + 8) * LDPH * (int)sizeof(uint32_t);
    cudaFuncSetAttribute(mtb_kernel, cudaFuncAttributeMaxDynamicSharedMemorySize, smemBytes);

    prep_kernel<<<256, 256>>>(Wq_w, Wk_w, Wv_w, fc_w);
    memprep_kernel<<<6, 256>>>(mem_k, mem_v);
    mtb_kernel<<<16384 / GG, 256, smemBytes>>>(x, Wq_b, Wk_b, Wv_b,
                                               fc_b, gamma, beta, alpha, out);
}